// round 2
// baseline (speedup 1.0000x reference)
#include <cuda_runtime.h>

#define NN      100000
#define EEDGES  1600000
#define KIN     128
#define HF      128      // HEADS * OUT_F
#define NHEADS  4

// ---------------- scratch (static device globals; no allocations) ----------------
__device__ __align__(16) float g_h[(size_t)NN * HF];        // 51.2 MB  h = xW
__device__ __align__(16) float g_asrc[NN * NHEADS];
__device__ __align__(16) float g_adst[NN * NHEADS];
__device__ unsigned g_m[NN * NHEADS];                        // encoded segment max
__device__ float    g_s[NN * NHEADS];                        // softmax denominator

// monotonic float<->uint encoding for atomicMax (handles negatives)
__device__ __forceinline__ unsigned enc_f(float f) {
    unsigned u = __float_as_uint(f);
    return (u & 0x80000000u) ? ~u : (u | 0x80000000u);
}
__device__ __forceinline__ float dec_f(unsigned u) {
    return __uint_as_float((u & 0x80000000u) ? (u & 0x7fffffffu) : ~u);
}

// ---------------- 1. zero output / denominators, init max buffer ----------------
__global__ void init_kernel(float4* __restrict__ out4, int n) {
    int i = blockIdx.x * blockDim.x + threadIdx.x;
    if (i < n * 32) out4[i] = make_float4(0.f, 0.f, 0.f, 0.f);
    if (i < n * NHEADS) { g_s[i] = 0.f; g_m[i] = 0u; }   // enc: 0 < enc(any finite)
}

// ---------------- 2. GEMM: g_h[n][128] = x[n][128] @ W[128][128] ----------------
// 128x128 block tile, K-chunks of 32, 256 threads, 8x8 micro-tile (split 4+4).
__global__ __launch_bounds__(256) void gemm_kernel(const float* __restrict__ x,
                                                   const float* __restrict__ W, int n) {
    __shared__ __align__(16) float xs[32][136];   // [k][row], padded
    __shared__ __align__(16) float ws[32][132];   // [k][col], padded
    int tid = threadIdx.x;
    int ty = tid >> 4, tx = tid & 15;
    int brow = blockIdx.x * 128;

    float acc[2][4][2][4];
    #pragma unroll
    for (int a = 0; a < 2; a++)
        #pragma unroll
        for (int b = 0; b < 4; b++)
            #pragma unroll
            for (int c = 0; c < 2; c++)
                #pragma unroll
                for (int d = 0; d < 4; d++) acc[a][b][c][d] = 0.f;

    for (int kc = 0; kc < 4; kc++) {
        int k0 = kc * 32;
        #pragma unroll
        for (int it = 0; it < 4; it++) {          // x tile: 128 rows x 32 k (transposed store)
            int f = tid + it * 256;
            int r = f >> 3, kq = f & 7;
            float4 v = make_float4(0.f, 0.f, 0.f, 0.f);
            if (brow + r < n)
                v = *(const float4*)(x + (size_t)(brow + r) * KIN + k0 + kq * 4);
            xs[kq * 4 + 0][r] = v.x; xs[kq * 4 + 1][r] = v.y;
            xs[kq * 4 + 2][r] = v.z; xs[kq * 4 + 3][r] = v.w;
        }
        #pragma unroll
        for (int it = 0; it < 4; it++) {          // W tile: 32 k x 128 cols
            int f = tid + it * 256;
            int k = f >> 5, c4 = f & 31;
            *(float4*)&ws[k][c4 * 4] =
                *(const float4*)(W + (size_t)(k0 + k) * HF + c4 * 4);
        }
        __syncthreads();

        #pragma unroll
        for (int k = 0; k < 32; k++) {
            float4 a0 = *(float4*)&xs[k][ty * 4];
            float4 a1 = *(float4*)&xs[k][64 + ty * 4];
            float4 b0 = *(float4*)&ws[k][tx * 4];
            float4 b1 = *(float4*)&ws[k][64 + tx * 4];
            float av[2][4] = {{a0.x, a0.y, a0.z, a0.w}, {a1.x, a1.y, a1.z, a1.w}};
            float bv[2][4] = {{b0.x, b0.y, b0.z, b0.w}, {b1.x, b1.y, b1.z, b1.w}};
            #pragma unroll
            for (int ri = 0; ri < 2; ri++)
                #pragma unroll
                for (int i = 0; i < 4; i++)
                    #pragma unroll
                    for (int ci = 0; ci < 2; ci++)
                        #pragma unroll
                        for (int j = 0; j < 4; j++)
                            acc[ri][i][ci][j] = fmaf(av[ri][i], bv[ci][j], acc[ri][i][ci][j]);
        }
        __syncthreads();
    }

    #pragma unroll
    for (int ri = 0; ri < 2; ri++)
        #pragma unroll
        for (int i = 0; i < 4; i++) {
            int r = brow + ri * 64 + ty * 4 + i;
            if (r < n) {
                #pragma unroll
                for (int ci = 0; ci < 2; ci++) {
                    float4 o = make_float4(acc[ri][i][ci][0], acc[ri][i][ci][1],
                                           acc[ri][i][ci][2], acc[ri][i][ci][3]);
                    *(float4*)(g_h + (size_t)r * HF + ci * 64 + tx * 4) = o;
                }
            }
        }
}

// ---------------- 3. per-node attention logits a_src, a_dst ----------------
__global__ void a_kernel(const float* __restrict__ att_src,
                         const float* __restrict__ att_dst, int n) {
    __shared__ float sa[HF], sd[HF];
    int t = threadIdx.x;                       // blockDim = 128
    sa[t] = att_src[t]; sd[t] = att_dst[t];
    __syncthreads();
    int nid = blockIdx.x * 128 + t;
    if (nid >= n) return;
    const float4* h4 = (const float4*)(g_h + (size_t)nid * HF);
    float as[NHEADS] = {0.f, 0.f, 0.f, 0.f};
    float ad[NHEADS] = {0.f, 0.f, 0.f, 0.f};
    #pragma unroll
    for (int c4 = 0; c4 < 32; c4++) {
        float4 v = h4[c4];
        int hd = c4 >> 3;
        const float* pa = &sa[c4 * 4];
        const float* pd = &sd[c4 * 4];
        as[hd] += v.x * pa[0] + v.y * pa[1] + v.z * pa[2] + v.w * pa[3];
        ad[hd] += v.x * pd[0] + v.y * pd[1] + v.z * pd[2] + v.w * pd[3];
    }
    #pragma unroll
    for (int hd = 0; hd < NHEADS; hd++) {
        g_asrc[nid * NHEADS + hd] = as[hd];
        g_adst[nid * NHEADS + hd] = ad[hd];
    }
}

// ---------------- 4. per-edge segment max (incl. self loops) ----------------
__global__ void edge_max_kernel(const int* __restrict__ ei, int E, int tot) {
    int i = blockIdx.x * blockDim.x + threadIdx.x;
    if (i >= tot) return;
    int s, d;
    if (i < E) { s = ei[i]; d = ei[E + i]; }
    else       { s = d = i - E; }
    float4 as = *(const float4*)&g_asrc[s * 4];
    float4 ad = *(const float4*)&g_adst[d * 4];
    float e[4] = {as.x + ad.x, as.y + ad.y, as.z + ad.z, as.w + ad.w};
    #pragma unroll
    for (int hd = 0; hd < 4; hd++) {
        float v = e[hd] > 0.f ? e[hd] : 0.2f * e[hd];
        atomicMax(&g_m[d * 4 + hd], enc_f(v));
    }
}

// ---------------- 5. per-edge softmax numerator + weighted scatter ----------------
// one warp per edge; lane L covers head L/8, features (L%8)*4..+3 via red.v4
__global__ void edge_acc_kernel(const int* __restrict__ ei,
                                float* __restrict__ out, int E, int tot) {
    int gt = blockIdx.x * blockDim.x + threadIdx.x;
    int warp = gt >> 5, lane = gt & 31;
    if (warp >= tot) return;
    int s, d;
    if (warp < E) { s = ei[warp]; d = ei[E + warp]; }
    else          { s = d = warp - E; }
    int hd = lane >> 3;
    float e = g_asrc[s * 4 + hd] + g_adst[d * 4 + hd];
    e = e > 0.f ? e : 0.2f * e;
    float m  = dec_f(g_m[d * 4 + hd]);
    float ex = __expf(e - m);
    if ((lane & 7) == 0) atomicAdd(&g_s[d * 4 + hd], ex);
    float4 hv = *(const float4*)(g_h + (size_t)s * HF + lane * 4);
    float4 v  = make_float4(hv.x * ex, hv.y * ex, hv.z * ex, hv.w * ex);
    atomicAdd((float4*)(out + (size_t)d * HF + lane * 4), v);   // sm_90+ vector red
}

// ---------------- 6. normalize + bias ----------------
__global__ void finalize_kernel(float* __restrict__ out,
                                const float* __restrict__ bias, int n) {
    int i = blockIdx.x * blockDim.x + threadIdx.x;
    if (i >= n * 32) return;
    int c4 = i & 31, nid = i >> 5, hd = c4 >> 3;
    float inv = 1.0f / (g_s[nid * 4 + hd] + 1e-16f);
    float4 v = *((float4*)out + i);
    float4 b = *((const float4*)bias + c4);
    v.x = v.x * inv + b.x; v.y = v.y * inv + b.y;
    v.z = v.z * inv + b.z; v.w = v.w * inv + b.w;
    *((float4*)out + i) = v;
}

// ---------------- launch ----------------
extern "C" void kernel_launch(void* const* d_in, const int* in_sizes, int n_in,
                              void* d_out, int out_size) {
    const float* x       = (const float*)d_in[0];
    const int*   ei      = (const int*)d_in[1];     // int32! (jax default x64-disabled)
    const float* W       = (const float*)d_in[2];
    const float* att_src = (const float*)d_in[3];
    const float* att_dst = (const float*)d_in[4];
    const float* bias    = (const float*)d_in[5];
    float* out = (float*)d_out;

    int n   = in_sizes[0] / KIN;     // 100000
    int E   = in_sizes[1] / 2;       // 1600000
    int tot = E + n;                 // edges + self loops

    init_kernel<<<(n * 32 + 255) / 256, 256>>>((float4*)out, n);
    gemm_kernel<<<(n + 127) / 128, 256>>>(x, W, n);
    a_kernel<<<(n + 127) / 128, 128>>>(att_src, att_dst, n);
    edge_max_kernel<<<(tot + 255) / 256, 256>>>(ei, E, tot);
    {
        long long threads = (long long)tot * 32;
        int blocks = (int)((threads + 255) / 256);
        edge_acc_kernel<<<blocks, 256>>>(ei, out, E, tot);
    }
    finalize_kernel<<<(n * 32 + 255) / 256, 256>>>(out, bias, n);
}